// round 9
// baseline (speedup 1.0000x reference)
#include <cuda_runtime.h>
#include <cuda_bf16.h>
#include <cstdint>
#include <cstddef>

#define Bz 512
#define Sz 128
#define Dz 128
#define Hz 1024
#define H3z 3072
#define Lz 128
#define BK 32
#define SKW 40
#define NSTG 4
#define BH (Bz*Hz)
#define NCTA 128
#define NTHR 512
#define ARR_STRIDE (64*SKW*2)            // bytes per 64xBK bf16 array (5120)
#define STG_STRIDE (4*ARR_STRIDE)        // 4 arrays per stage (20480)
#define TEAM_STRIDE (NSTG*STG_STRIDE)    // per-team ring (81920)
#define SCRATCH_OFF (2*TEAM_STRIDE)      // 163840
#define SMEM_DYN (SCRATCH_OFF + 64*64*4) // + 16KB f32 reduction scratch = 180224

// ---------------- device scratch (no cudaMalloc allowed) --------------------
__device__ __nv_bfloat16 g_w0h[Hz*Hz], g_w0l[Hz*Hz], g_w1h[Hz*Hz], g_w1l[Hz*Hz];
__device__ __nv_bfloat16 g_w2h[Hz*Hz], g_w2l[Hz*Hz];
__device__ __nv_bfloat16 g_whh_h[H3z*Hz], g_whh_l[H3z*Hz];
__device__ __nv_bfloat16 g_wih_h[H3z*Dz], g_wih_l[H3z*Dz];
__device__ __nv_bfloat16 g_muh[Lz*Hz], g_mul[Lz*Hz], g_lvh[Lz*Hz], g_lvl[Lz*Hz];
__device__ __nv_bfloat16 g_xh[Bz*Sz*Dz], g_xl[Bz*Sz*Dz];
__device__ __nv_bfloat16 g_yh[BH], g_yl[BH], g_t0h[BH], g_t0l[BH], g_t1h[BH], g_t1l[BH];
__device__ float g_h[BH], g_ka[5*BH], g_gi[Bz*H3z], g_gh[Bz*H3z];
__device__ unsigned g_count = 0;
__device__ unsigned g_gen = 0;

// ---------------- grid barrier (all 128 CTAs co-resident) -------------------
__device__ __forceinline__ void gsync() {
    __syncthreads();
    if (threadIdx.x == 0) {
        __threadfence();
        unsigned gen = *(volatile unsigned*)&g_gen;
        if (atomicAdd(&g_count, 1u) == gridDim.x - 1) {
            g_count = 0;
            __threadfence();
            *(volatile unsigned*)&g_gen = gen + 1;
        } else {
            while (*(volatile unsigned*)&g_gen == gen) { }
        }
        __threadfence();
    }
    __syncthreads();
}

// ---------------- GEMM engine ------------------------------------------------
struct GP {
    const __nv_bfloat16 *Ah, *Al, *Bh, *Bl;
    const float* bias;
    int N, K, lda, op, nk;          // op: 0=store f32, 1=tanh+split, 2=RK combine
    float *outF, *yF;
    __nv_bfloat16 *oh, *ol;
    const float *hb, *kb0, *kb1, *kb2, *kb3, *tp;
    float c0, c1, c2, c3, cc;
};

__device__ __forceinline__ uint32_t cvs(const void* p) {
    return (uint32_t)__cvta_generic_to_shared(p);
}
__device__ __forceinline__ void cp16(uint32_t s, const void* g) {
    asm volatile("cp.async.cg.shared.global [%0], [%1], 16;\n" :: "r"(s), "l"(g));
}
__device__ __forceinline__ void ldsm4(uint32_t a, uint32_t& r0, uint32_t& r1,
                                      uint32_t& r2, uint32_t& r3) {
    asm volatile("ldmatrix.sync.aligned.m8n8.x4.shared.b16 {%0,%1,%2,%3}, [%4];\n"
                 : "=r"(r0), "=r"(r1), "=r"(r2), "=r"(r3) : "r"(a));
}
__device__ __forceinline__ void mma(float* c, const uint32_t* a, uint32_t b0, uint32_t b1) {
    asm volatile(
        "mma.sync.aligned.m16n8k16.row.col.f32.bf16.bf16.f32 "
        "{%0,%1,%2,%3}, {%4,%5,%6,%7}, {%8,%9}, {%0,%1,%2,%3};\n"
        : "+f"(c[0]), "+f"(c[1]), "+f"(c[2]), "+f"(c[3])
        : "r"(a[0]), "r"(a[1]), "r"(a[2]), "r"(a[3]), "r"(b0), "r"(b1));
}
__device__ __forceinline__ void tbar(int team) {
    asm volatile("bar.sync %0, 256;\n" :: "r"(team + 1));
}

extern __shared__ __nv_bfloat16 smraw[];

// C[512,N] = epi(A@B^T + bias); A=[512,K] hi/lo, B=[N,K] hi/lo. Tile-strided.
// 512 threads: two 8-warp k-teams, each with its own 4-stage cp.async ring over
// half the K range; fp32 accumulator reduction through smem scratch; team 0
// runs the fused epilogue.
__device__ __noinline__ void do_gemm(const GP& p) {
    const int tid = threadIdx.x;
    const int warp = tid >> 5, lane = tid & 31;
    const int team = warp >> 3;                 // 0 or 1
    const int wt = warp & 7;                    // warp within team
    const int ttid = tid & 255;                 // thread within team
    const int m0 = (wt & 1) * 32, n0 = (wt >> 1) * 16;
    const int arow = m0 + (lane & 15), acol = (lane >> 4) << 3;
    const int brow = n0 + ((lane >> 4) << 3) + (lane & 7), bcol = ((lane >> 3) & 1) << 3;
    const int lr = ttid >> 2, lc = ttid & 3;
    const uint32_t so = (uint32_t)((lr * SKW + lc * 8) * 2);
    const int ntile = (p.N >> 6) * 8;
    const int KT2 = p.K / BK / 2;               // per-team iterations
    const int kbase = team * (p.K >> 1);
    const uint32_t tbase = cvs(smraw) + (uint32_t)(team * TEAM_STRIDE);
    float* scr = (float*)((char*)smraw + SCRATCH_OFF);

    float hs = 0.f;
    if (p.op == 2) hs = (p.tp[1] - p.tp[0]) * 0.25f;

    for (int tile = blockIdx.x; tile < ntile; tile += gridDim.x) {
        const int bm = (tile & 7) << 6;
        const int bn = (tile >> 3) << 6;
        const __nv_bfloat16* gAh = p.Ah + (size_t)(bm + lr) * p.lda + kbase + lc * 8;
        const __nv_bfloat16* gAl = p.Al + (size_t)(bm + lr) * p.lda + kbase + lc * 8;
        const __nv_bfloat16* gBh = p.Bh + (size_t)(bn + lr) * p.K + kbase + lc * 8;
        const __nv_bfloat16* gBl = p.Bl + (size_t)(bn + lr) * p.K + kbase + lc * 8;

        float acc[2][2][4];
        #pragma unroll
        for (int a = 0; a < 2; a++)
            #pragma unroll
            for (int b = 0; b < 2; b++)
                #pragma unroll
                for (int i = 0; i < 4; i++) acc[a][b][i] = 0.f;

        auto load = [&](int st, int kt) {
            const uint32_t sb = tbase + (uint32_t)(st * STG_STRIDE) + so;
            // clamp: prologue stages beyond KT2-1 load in-bounds junk, never consumed
            const int ko = (kt < KT2 ? kt : KT2 - 1) * BK;
            cp16(sb + 0 * ARR_STRIDE, gAh + ko);
            cp16(sb + 1 * ARR_STRIDE, gAl + ko);
            cp16(sb + 2 * ARR_STRIDE, gBh + ko);
            cp16(sb + 3 * ARR_STRIDE, gBl + ko);
        };

        tbar(team);        // this team's previous-tile consumers are done
        load(0, 0);
        asm volatile("cp.async.commit_group;\n");
        load(1, 1);
        asm volatile("cp.async.commit_group;\n");
        load(2, 2);
        asm volatile("cp.async.commit_group;\n");

        for (int kt = 0; kt < KT2; ++kt) {
            asm volatile("cp.async.wait_group 2;\n");   // stage kt landed (in-order)
            tbar(team);                                 // publish within team
            if (kt + 3 < KT2) load((kt + 3) & 3, kt + 3);
            asm volatile("cp.async.commit_group;\n");

            const int st = kt & 3;
            const uint32_t base = tbase + (uint32_t)(st * STG_STRIDE);
            const uint32_t bAh = base, bAl = base + ARR_STRIDE;
            const uint32_t bBh = base + 2 * ARR_STRIDE, bBl = base + 3 * ARR_STRIDE;
            #pragma unroll
            for (int k16 = 0; k16 < 2; k16++) {
                uint32_t ah[2][4], al[2][4], bh[4], bl[4];
                #pragma unroll
                for (int mf = 0; mf < 2; mf++) {
                    uint32_t off = (uint32_t)(((arow + mf * 16) * SKW + acol + k16 * 16) * 2);
                    ldsm4(bAh + off, ah[mf][0], ah[mf][1], ah[mf][2], ah[mf][3]);
                    ldsm4(bAl + off, al[mf][0], al[mf][1], al[mf][2], al[mf][3]);
                }
                uint32_t boff = (uint32_t)((brow * SKW + bcol + k16 * 16) * 2);
                ldsm4(bBh + boff, bh[0], bh[1], bh[2], bh[3]);
                ldsm4(bBl + boff, bl[0], bl[1], bl[2], bl[3]);
                // product-major: consecutive writes to any acc are 4 slots apart
                #pragma unroll
                for (int mf = 0; mf < 2; mf++)
                    #pragma unroll
                    for (int nf = 0; nf < 2; nf++)
                        mma(acc[mf][nf], ah[mf], bh[nf * 2], bh[nf * 2 + 1]);
                #pragma unroll
                for (int mf = 0; mf < 2; mf++)
                    #pragma unroll
                    for (int nf = 0; nf < 2; nf++)
                        mma(acc[mf][nf], ah[mf], bl[nf * 2], bl[nf * 2 + 1]);
                #pragma unroll
                for (int mf = 0; mf < 2; mf++)
                    #pragma unroll
                    for (int nf = 0; nf < 2; nf++)
                        mma(acc[mf][nf], al[mf], bh[nf * 2], bh[nf * 2 + 1]);
            }
        }

        // ---- cross-team reduction + epilogue (team 0 finishes) -------------
        __syncthreads();
        if (team == 1) {
            float* s = scr + ttid * 16;
            #pragma unroll
            for (int mf = 0; mf < 2; mf++)
                #pragma unroll
                for (int nf = 0; nf < 2; nf++)
                    #pragma unroll
                    for (int i = 0; i < 4; i++)
                        s[(mf * 2 + nf) * 4 + i] = acc[mf][nf][i];
        }
        __syncthreads();
        if (team == 0) {
            const float* s = scr + ttid * 16;
            #pragma unroll
            for (int mf = 0; mf < 2; mf++)
                #pragma unroll
                for (int nf = 0; nf < 2; nf++)
                    #pragma unroll
                    for (int i = 0; i < 4; i++) {
                        int gm = bm + m0 + mf * 16 + (lane >> 2) + (i >> 1) * 8;
                        int gn = bn + n0 + nf * 8 + (lane & 3) * 2 + (i & 1);
                        size_t idx = (size_t)gm * p.N + gn;
                        float v = acc[mf][nf][i] + s[(mf * 2 + nf) * 4 + i] + p.bias[gn];
                        if (p.op == 0) {
                            p.outF[idx] = v;
                        } else if (p.op == 1) {
                            float tv = tanhf(v);
                            __nv_bfloat16 hi = __float2bfloat16(tv);
                            p.oh[idx] = hi;
                            p.ol[idx] = __float2bfloat16(tv - __bfloat162float(hi));
                        } else {
                            if (p.outF) p.outF[idx] = v;
                            float y = p.hb[idx];
                            if (p.nk > 0) y = fmaf(hs * p.c0, p.kb0[idx], y);
                            if (p.nk > 1) y = fmaf(hs * p.c1, p.kb1[idx], y);
                            if (p.nk > 2) y = fmaf(hs * p.c2, p.kb2[idx], y);
                            if (p.nk > 3) y = fmaf(hs * p.c3, p.kb3[idx], y);
                            y = fmaf(hs * p.cc, v, y);
                            __nv_bfloat16 hi = __float2bfloat16(y);
                            p.oh[idx] = hi;
                            p.ol[idx] = __float2bfloat16(y - __bfloat162float(hi));
                            if (p.yF) p.yF[idx] = y;
                        }
                    }
        }
    }
}

// ---------------- elementwise device helpers --------------------------------
__device__ void dsplit(const float* __restrict__ s, __nv_bfloat16* __restrict__ hi,
                       __nv_bfloat16* __restrict__ lo, int n) {
    for (int i = blockIdx.x * blockDim.x + threadIdx.x; i < n; i += gridDim.x * blockDim.x) {
        float v = s[i];
        __nv_bfloat16 h = __float2bfloat16(v);
        hi[i] = h;
        lo[i] = __float2bfloat16(v - __bfloat162float(h));
    }
}

__device__ void gru_ew() {
    for (int idx = blockIdx.x * blockDim.x + threadIdx.x; idx < BH;
         idx += gridDim.x * blockDim.x) {
        int m = idx >> 10, n = idx & (Hz - 1);
        size_t o = (size_t)m * H3z + n;
        float r = 1.f / (1.f + expf(-(g_gi[o] + g_gh[o])));
        float z = 1.f / (1.f + expf(-(g_gi[o + Hz] + g_gh[o + Hz])));
        float nn = tanhf(g_gi[o + 2 * Hz] + r * g_gh[o + 2 * Hz]);
        float hv = (1.f - z) * nn + z * g_h[idx];
        g_h[idx] = hv;
        __nv_bfloat16 hi = __float2bfloat16(hv);
        g_yh[idx] = hi;
        g_yl[idx] = __float2bfloat16(hv - __bfloat162float(hi));
    }
}

// dopri5 stage tables: stage s computes k_{s+1}; combine gives y for next stage
__device__ const float c_CP[6][4] = {
    {0, 0, 0, 0},
    {3.f/40, 0, 0, 0},
    {44.f/45, -56.f/15, 0, 0},
    {19372.f/6561, -25360.f/2187, 64448.f/6561, 0},
    {9017.f/3168, -355.f/33, 46732.f/5247, 49.f/176},
    {35.f/384, 500.f/1113, 125.f/192, -2187.f/6784}};
__device__ const float c_CC[6] = {1.f/5, 9.f/40, 32.f/9, -212.f/729, -5103.f/18656, 11.f/84};
__device__ const int c_NK[6] = {0, 1, 2, 3, 4, 4};

__device__ void feval(const float* tp, int s,
                      const float* b0, const float* b1, const float* b2) {
    GP p{};
    p.Ah = g_yh; p.Al = g_yl; p.Bh = g_w0h; p.Bl = g_w0l; p.bias = b0;
    p.N = Hz; p.K = Hz; p.lda = Hz; p.op = 1; p.oh = g_t0h; p.ol = g_t0l;
    do_gemm(p);
    gsync();
    p.Ah = g_t0h; p.Al = g_t0l; p.Bh = g_w1h; p.Bl = g_w1l; p.bias = b1;
    p.oh = g_t1h; p.ol = g_t1l;
    do_gemm(p);
    gsync();
    GP q{};
    q.Ah = g_t1h; q.Al = g_t1l; q.Bh = g_w2h; q.Bl = g_w2l; q.bias = b2;
    q.N = Hz; q.K = Hz; q.lda = Hz; q.op = 2; q.oh = g_yh; q.ol = g_yl;
    q.hb = g_h; q.tp = tp; q.nk = c_NK[s]; q.cc = c_CC[s];
    q.c0 = c_CP[s][0]; q.c1 = c_CP[s][1]; q.c2 = c_CP[s][2]; q.c3 = c_CP[s][3];
    if (s == 5) {
        q.kb0 = g_ka; q.kb1 = g_ka + 2 * BH; q.kb2 = g_ka + 3 * BH; q.kb3 = g_ka + 4 * BH;
        q.yF = g_h; q.outF = nullptr;
    } else {
        q.kb0 = g_ka; q.kb1 = g_ka + BH; q.kb2 = g_ka + 2 * BH; q.kb3 = g_ka + 3 * BH;
        q.outF = g_ka + s * BH;
    }
    do_gemm(q);
    gsync();
}

__device__ void do_gru(int i, const float* bih, const float* bhh) {
    GP p{};
    p.Ah = g_xh + i * Dz; p.Al = g_xl + i * Dz; p.lda = Sz * Dz;
    p.Bh = g_wih_h; p.Bl = g_wih_l; p.bias = bih; p.N = H3z; p.K = Dz;
    p.op = 0; p.outF = g_gi;
    do_gemm(p);
    GP q{};
    q.Ah = g_yh; q.Al = g_yl; q.lda = Hz;
    q.Bh = g_whh_h; q.Bl = g_whh_l; q.bias = bhh; q.N = H3z; q.K = Hz;
    q.op = 0; q.outF = g_gh;
    do_gemm(q);
    gsync();
    gru_ew();
    gsync();
}

// ---------------- the megakernel ---------------------------------------------
__global__ void __launch_bounds__(NTHR, 1) mega_kernel(
    const float* x, const float* t, const float* wih, const float* whh,
    const float* bih, const float* bhh, const float* w0, const float* b0,
    const float* w1, const float* b1, const float* w2, const float* b2,
    const float* muw, const float* mub, const float* lvw, const float* lvb,
    float* out)
{
    // prologue: split everything to bf16 hi/lo; init h state
    dsplit(w0, g_w0h, g_w0l, Hz * Hz);
    dsplit(w1, g_w1h, g_w1l, Hz * Hz);
    dsplit(w2, g_w2h, g_w2l, Hz * Hz);
    dsplit(whh, g_whh_h, g_whh_l, H3z * Hz);
    dsplit(wih, g_wih_h, g_wih_l, H3z * Dz);
    dsplit(muw, g_muh, g_mul, Lz * Hz);
    dsplit(lvw, g_lvh, g_lvl, Lz * Hz);
    dsplit(x, g_xh, g_xl, Bz * Sz * Dz);
    for (int i = blockIdx.x * blockDim.x + threadIdx.x; i < BH;
         i += gridDim.x * blockDim.x) {
        g_h[i] = 0.f;
        g_yh[i] = __float2bfloat16(0.f);
        g_yl[i] = __float2bfloat16(0.f);
    }
    gsync();

    do_gru(0, bih, bhh);
    #pragma unroll 1
    for (int i = 1; i < Sz; i++) {
        const float* tp = t + (i - 1);
        #pragma unroll 1
        for (int sub = 0; sub < 4; sub++)
            #pragma unroll 1
            for (int s = 0; s < 6; s++) feval(tp, s, b0, b1, b2);
        do_gru(i, bih, bhh);
    }

    GP p{};
    p.Ah = g_yh; p.Al = g_yl; p.lda = Hz; p.Bh = g_muh; p.Bl = g_mul; p.bias = mub;
    p.N = Lz; p.K = Hz; p.op = 0; p.outF = out;
    do_gemm(p);
    GP q{};
    q.Ah = g_yh; q.Al = g_yl; q.lda = Hz; q.Bh = g_lvh; q.Bl = g_lvl; q.bias = lvb;
    q.N = Lz; q.K = Hz; q.op = 0; q.outF = out + Bz * Lz;
    do_gemm(q);
}

// ---------------- host ---------------------------------------------------------
extern "C" void kernel_launch(void* const* d_in, const int* in_sizes, int n_in,
                              void* d_out, int out_size) {
    (void)in_sizes; (void)n_in; (void)out_size;
    cudaFuncSetAttribute(mega_kernel, cudaFuncAttributeMaxDynamicSharedMemorySize,
                         SMEM_DYN);
    mega_kernel<<<NCTA, NTHR, SMEM_DYN>>>(
        (const float*)d_in[0],  (const float*)d_in[1],  (const float*)d_in[2],
        (const float*)d_in[3],  (const float*)d_in[4],  (const float*)d_in[5],
        (const float*)d_in[6],  (const float*)d_in[7],  (const float*)d_in[8],
        (const float*)d_in[9],  (const float*)d_in[10], (const float*)d_in[11],
        (const float*)d_in[12], (const float*)d_in[13], (const float*)d_in[14],
        (const float*)d_in[15], (float*)d_out);
}

// round 11
// speedup vs baseline: 1.0847x; 1.0847x over previous
#include <cuda_runtime.h>
#include <cuda_bf16.h>
#include <cstdint>
#include <cstddef>

#define Bz 512
#define Sz 128
#define Dz 128
#define Hz 1024
#define H3z 3072
#define Lz 128
#define BK 32
#define SKW 40
#define NSTG 4
#define BH (Bz*Hz)
#define NCTA 128
#define NTHR 256
#define NGRP 8
#define GSZ 16                            // CTAs per row-group
#define ARR_STRIDE (64*SKW*2)             // bytes per 64xBK bf16 array
#define STG_STRIDE (4*ARR_STRIDE)         // 4 arrays per stage
#define SMEM_DYN (NSTG*STG_STRIDE)        // 81920 bytes

// ---------------- device scratch (no cudaMalloc allowed) --------------------
__device__ __nv_bfloat16 g_w0h[Hz*Hz], g_w0l[Hz*Hz], g_w1h[Hz*Hz], g_w1l[Hz*Hz];
__device__ __nv_bfloat16 g_w2h[Hz*Hz], g_w2l[Hz*Hz];
__device__ __nv_bfloat16 g_whh_h[H3z*Hz], g_whh_l[H3z*Hz];
__device__ __nv_bfloat16 g_wih_h[H3z*Dz], g_wih_l[H3z*Dz];
__device__ __nv_bfloat16 g_muh[Lz*Hz], g_mul[Lz*Hz], g_lvh[Lz*Hz], g_lvl[Lz*Hz];
__device__ __nv_bfloat16 g_xh[Bz*Sz*Dz], g_xl[Bz*Sz*Dz];
__device__ __nv_bfloat16 g_yh[BH], g_yl[BH], g_t0h[BH], g_t0l[BH], g_t1h[BH], g_t1l[BH];
__device__ float g_h[BH], g_ka[5*BH], g_gi[Bz*H3z], g_gh[Bz*H3z];
__device__ unsigned g_count = 0;
__device__ unsigned g_gen = 0;
__device__ unsigned g_gcnt[NGRP*32];      // per-group barrier state, 128B apart
__device__ unsigned g_ggen[NGRP*32];

// ---------------- global barrier (prologue only) -----------------------------
__device__ __forceinline__ void gsync() {
    __syncthreads();
    if (threadIdx.x == 0) {
        __threadfence();
        unsigned gen = *(volatile unsigned*)&g_gen;
        if (atomicAdd(&g_count, 1u) == gridDim.x - 1) {
            g_count = 0;
            __threadfence();
            *(volatile unsigned*)&g_gen = gen + 1;
        } else {
            while (*(volatile unsigned*)&g_gen == gen) { }
        }
        __threadfence();
    }
    __syncthreads();
}

// ---------------- per-row-group barrier (16 CTAs) ----------------------------
__device__ __forceinline__ void gbar() {
    const int g = blockIdx.x >> 4;
    __syncthreads();
    if (threadIdx.x == 0) {
        unsigned* cnt = &g_gcnt[g * 32];
        volatile unsigned* gen = (volatile unsigned*)&g_ggen[g * 32];
        __threadfence();
        unsigned cur = *gen;
        if (atomicAdd(cnt, 1u) == GSZ - 1) {
            *cnt = 0;
            __threadfence();
            *gen = cur + 1;
        } else {
            while (*gen == cur) { }
        }
        __threadfence();
    }
    __syncthreads();
}

// ---------------- GEMM engine ------------------------------------------------
struct GP {
    const __nv_bfloat16 *Ah, *Al, *Bh, *Bl;
    const float* bias;
    int N, K, lda, op, nk;          // op: 0=store f32, 1=tanh+split, 2=RK combine
    float *outF, *yF;
    __nv_bfloat16 *oh, *ol;
    const float *hb, *kb0, *kb1, *kb2, *kb3, *tp;
    float c0, c1, c2, c3, cc;
};

__device__ __forceinline__ uint32_t cvs(const void* p) {
    return (uint32_t)__cvta_generic_to_shared(p);
}
__device__ __forceinline__ void cp16(uint32_t s, const void* g) {
    asm volatile("cp.async.cg.shared.global [%0], [%1], 16;\n" :: "r"(s), "l"(g));
}
__device__ __forceinline__ void ldsm4(uint32_t a, uint32_t& r0, uint32_t& r1,
                                      uint32_t& r2, uint32_t& r3) {
    asm volatile("ldmatrix.sync.aligned.m8n8.x4.shared.b16 {%0,%1,%2,%3}, [%4];\n"
                 : "=r"(r0), "=r"(r1), "=r"(r2), "=r"(r3) : "r"(a));
}
__device__ __forceinline__ void mma(float* c, const uint32_t* a, uint32_t b0, uint32_t b1) {
    asm volatile(
        "mma.sync.aligned.m16n8k16.row.col.f32.bf16.bf16.f32 "
        "{%0,%1,%2,%3}, {%4,%5,%6,%7}, {%8,%9}, {%0,%1,%2,%3};\n"
        : "+f"(c[0]), "+f"(c[1]), "+f"(c[2]), "+f"(c[3])
        : "r"(a[0]), "r"(a[1]), "r"(a[2]), "r"(a[3]), "r"(b0), "r"(b1));
}

extern __shared__ __nv_bfloat16 smraw[];

// C[rows 64g..64g+64, N] = epi(A@B^T + bias). Group g's 16 CTAs cover the bn
// tiles (member m takes bn = m, m+16, ...). Engine: 64x64 tile, BK=32,
// 4-stage cp.async ring (wait_group 2), product-major MMA order.
__device__ __noinline__ void do_gemm(const GP& p) {
    const int tid = threadIdx.x;
    const int warp = tid >> 5, lane = tid & 31;
    const int m0 = (warp & 1) * 32, n0 = (warp >> 1) * 16;
    const int arow = m0 + (lane & 15), acol = (lane >> 4) << 3;
    const int brow = n0 + ((lane >> 4) << 3) + (lane & 7), bcol = ((lane >> 3) & 1) << 3;
    const int lr = tid >> 2, lc = tid & 3;
    const uint32_t so = (uint32_t)((lr * SKW + lc * 8) * 2);
    const int memb = blockIdx.x & 15;
    const int bm = (blockIdx.x >> 4) << 6;     // group-owned 64-row slice
    const int nbn = p.N >> 6;
    const int KT = p.K / BK;
    const uint32_t sbase = cvs(smraw);

    float hs = 0.f;
    if (p.op == 2) hs = (p.tp[1] - p.tp[0]) * 0.25f;

    for (int j = memb; j < nbn; j += GSZ) {
        const int bn = j << 6;
        const __nv_bfloat16* gAh = p.Ah + (size_t)(bm + lr) * p.lda + lc * 8;
        const __nv_bfloat16* gAl = p.Al + (size_t)(bm + lr) * p.lda + lc * 8;
        const __nv_bfloat16* gBh = p.Bh + (size_t)(bn + lr) * p.K + lc * 8;
        const __nv_bfloat16* gBl = p.Bl + (size_t)(bn + lr) * p.K + lc * 8;

        float acc[2][2][4];
        #pragma unroll
        for (int a = 0; a < 2; a++)
            #pragma unroll
            for (int b = 0; b < 2; b++)
                #pragma unroll
                for (int i = 0; i < 4; i++) acc[a][b][i] = 0.f;

        auto load = [&](int st, int kt) {
            const uint32_t sb = sbase + (uint32_t)(st * STG_STRIDE) + so;
            const int ko = kt * BK;
            cp16(sb + 0 * ARR_STRIDE, gAh + ko);
            cp16(sb + 1 * ARR_STRIDE, gAl + ko);
            cp16(sb + 2 * ARR_STRIDE, gBh + ko);
            cp16(sb + 3 * ARR_STRIDE, gBl + ko);
        };

        __syncthreads();   // previous tile's consumers done before overwriting smem
        load(0, 0);
        asm volatile("cp.async.commit_group;\n");
        if (KT > 1) load(1, 1);
        asm volatile("cp.async.commit_group;\n");
        if (KT > 2) load(2, 2);
        asm volatile("cp.async.commit_group;\n");

        for (int kt = 0; kt < KT; ++kt) {
            asm volatile("cp.async.wait_group 2;\n");   // stage kt landed (in-order)
            __syncthreads();                            // publish; all warps done kt-1
            if (kt + 3 < KT) load((kt + 3) & 3, kt + 3);
            asm volatile("cp.async.commit_group;\n");

            const int st = kt & 3;
            const uint32_t base = sbase + (uint32_t)(st * STG_STRIDE);
            const uint32_t bAh = base, bAl = base + ARR_STRIDE;
            const uint32_t bBh = base + 2 * ARR_STRIDE, bBl = base + 3 * ARR_STRIDE;
            #pragma unroll
            for (int k16 = 0; k16 < 2; k16++) {
                uint32_t ah[2][4], al[2][4], bh[4], bl[4];
                #pragma unroll
                for (int mf = 0; mf < 2; mf++) {
                    uint32_t off = (uint32_t)(((arow + mf * 16) * SKW + acol + k16 * 16) * 2);
                    ldsm4(bAh + off, ah[mf][0], ah[mf][1], ah[mf][2], ah[mf][3]);
                    ldsm4(bAl + off, al[mf][0], al[mf][1], al[mf][2], al[mf][3]);
                }
                uint32_t boff = (uint32_t)((brow * SKW + bcol + k16 * 16) * 2);
                ldsm4(bBh + boff, bh[0], bh[1], bh[2], bh[3]);
                ldsm4(bBl + boff, bl[0], bl[1], bl[2], bl[3]);
                // product-major: consecutive writes to any acc are 4 slots apart
                #pragma unroll
                for (int mf = 0; mf < 2; mf++)
                    #pragma unroll
                    for (int nf = 0; nf < 2; nf++)
                        mma(acc[mf][nf], ah[mf], bh[nf * 2], bh[nf * 2 + 1]);
                #pragma unroll
                for (int mf = 0; mf < 2; mf++)
                    #pragma unroll
                    for (int nf = 0; nf < 2; nf++)
                        mma(acc[mf][nf], ah[mf], bl[nf * 2], bl[nf * 2 + 1]);
                #pragma unroll
                for (int mf = 0; mf < 2; mf++)
                    #pragma unroll
                    for (int nf = 0; nf < 2; nf++)
                        mma(acc[mf][nf], al[mf], bh[nf * 2], bh[nf * 2 + 1]);
            }
        }

        #pragma unroll
        for (int mf = 0; mf < 2; mf++)
            #pragma unroll
            for (int nf = 0; nf < 2; nf++)
                #pragma unroll
                for (int i = 0; i < 4; i++) {
                    int gm = bm + m0 + mf * 16 + (lane >> 2) + (i >> 1) * 8;
                    int gn = bn + n0 + nf * 8 + (lane & 3) * 2 + (i & 1);
                    size_t idx = (size_t)gm * p.N + gn;
                    float v = acc[mf][nf][i] + p.bias[gn];
                    if (p.op == 0) {
                        p.outF[idx] = v;
                    } else if (p.op == 1) {
                        float tv = tanhf(v);
                        __nv_bfloat16 hi = __float2bfloat16(tv);
                        p.oh[idx] = hi;
                        p.ol[idx] = __float2bfloat16(tv - __bfloat162float(hi));
                    } else {
                        if (p.outF) p.outF[idx] = v;
                        float y = p.hb[idx];
                        if (p.nk > 0) y = fmaf(hs * p.c0, p.kb0[idx], y);
                        if (p.nk > 1) y = fmaf(hs * p.c1, p.kb1[idx], y);
                        if (p.nk > 2) y = fmaf(hs * p.c2, p.kb2[idx], y);
                        if (p.nk > 3) y = fmaf(hs * p.c3, p.kb3[idx], y);
                        y = fmaf(hs * p.cc, v, y);
                        __nv_bfloat16 hi = __float2bfloat16(y);
                        p.oh[idx] = hi;
                        p.ol[idx] = __float2bfloat16(y - __bfloat162float(hi));
                        if (p.yF) p.yF[idx] = y;
                    }
                }
    }
}

// ---------------- elementwise device helpers --------------------------------
__device__ void dsplit(const float* __restrict__ s, __nv_bfloat16* __restrict__ hi,
                       __nv_bfloat16* __restrict__ lo, int n) {
    for (int i = blockIdx.x * blockDim.x + threadIdx.x; i < n; i += gridDim.x * blockDim.x) {
        float v = s[i];
        __nv_bfloat16 h = __float2bfloat16(v);
        hi[i] = h;
        lo[i] = __float2bfloat16(v - __bfloat162float(h));
    }
}

// group-partitioned GRU elementwise: group g handles its own 64 batch rows
__device__ void gru_ew() {
    const int memb = blockIdx.x & 15;
    const int base = (blockIdx.x >> 4) * 64 * Hz;
    for (int k = memb * NTHR + threadIdx.x; k < 64 * Hz; k += GSZ * NTHR) {
        int idx = base + k;
        int m = idx >> 10, n = idx & (Hz - 1);
        size_t o = (size_t)m * H3z + n;
        float r = 1.f / (1.f + expf(-(g_gi[o] + g_gh[o])));
        float z = 1.f / (1.f + expf(-(g_gi[o + Hz] + g_gh[o + Hz])));
        float nn = tanhf(g_gi[o + 2 * Hz] + r * g_gh[o + 2 * Hz]);
        float hv = (1.f - z) * nn + z * g_h[idx];
        g_h[idx] = hv;
        __nv_bfloat16 hi = __float2bfloat16(hv);
        g_yh[idx] = hi;
        g_yl[idx] = __float2bfloat16(hv - __bfloat162float(hi));
    }
}

// dopri5 stage tables: stage s computes k_{s+1}; combine gives y for next stage
__device__ const float c_CP[6][4] = {
    {0, 0, 0, 0},
    {3.f/40, 0, 0, 0},
    {44.f/45, -56.f/15, 0, 0},
    {19372.f/6561, -25360.f/2187, 64448.f/6561, 0},
    {9017.f/3168, -355.f/33, 46732.f/5247, 49.f/176},
    {35.f/384, 500.f/1113, 125.f/192, -2187.f/6784}};
__device__ const float c_CC[6] = {1.f/5, 9.f/40, 32.f/9, -212.f/729, -5103.f/18656, 11.f/84};
__device__ const int c_NK[6] = {0, 1, 2, 3, 4, 4};

__device__ void feval(const float* tp, int s,
                      const float* b0, const float* b1, const float* b2) {
    GP p{};
    p.Ah = g_yh; p.Al = g_yl; p.Bh = g_w0h; p.Bl = g_w0l; p.bias = b0;
    p.N = Hz; p.K = Hz; p.lda = Hz; p.op = 1; p.oh = g_t0h; p.ol = g_t0l;
    do_gemm(p);
    gbar();
    p.Ah = g_t0h; p.Al = g_t0l; p.Bh = g_w1h; p.Bl = g_w1l; p.bias = b1;
    p.oh = g_t1h; p.ol = g_t1l;
    do_gemm(p);
    gbar();
    GP q{};
    q.Ah = g_t1h; q.Al = g_t1l; q.Bh = g_w2h; q.Bl = g_w2l; q.bias = b2;
    q.N = Hz; q.K = Hz; q.lda = Hz; q.op = 2; q.oh = g_yh; q.ol = g_yl;
    q.hb = g_h; q.tp = tp; q.nk = c_NK[s]; q.cc = c_CC[s];
    q.c0 = c_CP[s][0]; q.c1 = c_CP[s][1]; q.c2 = c_CP[s][2]; q.c3 = c_CP[s][3];
    if (s == 5) {
        q.kb0 = g_ka; q.kb1 = g_ka + 2 * BH; q.kb2 = g_ka + 3 * BH; q.kb3 = g_ka + 4 * BH;
        q.yF = g_h; q.outF = nullptr;
    } else {
        q.kb0 = g_ka; q.kb1 = g_ka + BH; q.kb2 = g_ka + 2 * BH; q.kb3 = g_ka + 3 * BH;
        q.outF = g_ka + s * BH;
    }
    do_gemm(q);
    gbar();
}

__device__ void do_gru(int i, const float* bih, const float* bhh) {
    GP p{};
    p.Ah = g_xh + i * Dz; p.Al = g_xl + i * Dz; p.lda = Sz * Dz;
    p.Bh = g_wih_h; p.Bl = g_wih_l; p.bias = bih; p.N = H3z; p.K = Dz;
    p.op = 0; p.outF = g_gi;
    do_gemm(p);
    GP q{};
    q.Ah = g_yh; q.Al = g_yl; q.lda = Hz;
    q.Bh = g_whh_h; q.Bl = g_whh_l; q.bias = bhh; q.N = H3z; q.K = Hz;
    q.op = 0; q.outF = g_gh;
    do_gemm(q);
    gbar();
    gru_ew();
    gbar();
}

// ---------------- the megakernel ---------------------------------------------
__global__ void __launch_bounds__(NTHR, 1) mega_kernel(
    const float* x, const float* t, const float* wih, const float* whh,
    const float* bih, const float* bhh, const float* w0, const float* b0,
    const float* w1, const float* b1, const float* w2, const float* b2,
    const float* muw, const float* mub, const float* lvw, const float* lvb,
    float* out)
{
    // prologue: split everything to bf16 hi/lo; init h state (global, once)
    dsplit(w0, g_w0h, g_w0l, Hz * Hz);
    dsplit(w1, g_w1h, g_w1l, Hz * Hz);
    dsplit(w2, g_w2h, g_w2l, Hz * Hz);
    dsplit(whh, g_whh_h, g_whh_l, H3z * Hz);
    dsplit(wih, g_wih_h, g_wih_l, H3z * Dz);
    dsplit(muw, g_muh, g_mul, Lz * Hz);
    dsplit(lvw, g_lvh, g_lvl, Lz * Hz);
    dsplit(x, g_xh, g_xl, Bz * Sz * Dz);
    for (int i = blockIdx.x * blockDim.x + threadIdx.x; i < BH;
         i += gridDim.x * blockDim.x) {
        g_h[i] = 0.f;
        g_yh[i] = __float2bfloat16(0.f);
        g_yl[i] = __float2bfloat16(0.f);
    }
    gsync();   // the only global barrier; groups run independently after this

    do_gru(0, bih, bhh);
    #pragma unroll 1
    for (int i = 1; i < Sz; i++) {
        const float* tp = t + (i - 1);
        #pragma unroll 1
        for (int sub = 0; sub < 4; sub++)
            #pragma unroll 1
            for (int s = 0; s < 6; s++) feval(tp, s, b0, b1, b2);
        do_gru(i, bih, bhh);
    }

    GP p{};
    p.Ah = g_yh; p.Al = g_yl; p.lda = Hz; p.Bh = g_muh; p.Bl = g_mul; p.bias = mub;
    p.N = Lz; p.K = Hz; p.op = 0; p.outF = out;
    do_gemm(p);
    GP q{};
    q.Ah = g_yh; q.Al = g_yl; q.lda = Hz; q.Bh = g_lvh; q.Bl = g_lvl; q.bias = lvb;
    q.N = Lz; q.K = Hz; q.op = 0; q.outF = out + Bz * Lz;
    do_gemm(q);
}

// ---------------- host ---------------------------------------------------------
extern "C" void kernel_launch(void* const* d_in, const int* in_sizes, int n_in,
                              void* d_out, int out_size) {
    (void)in_sizes; (void)n_in; (void)out_size;
    cudaFuncSetAttribute(mega_kernel, cudaFuncAttributeMaxDynamicSharedMemorySize,
                         SMEM_DYN);
    mega_kernel<<<NCTA, NTHR, SMEM_DYN>>>(
        (const float*)d_in[0],  (const float*)d_in[1],  (const float*)d_in[2],
        (const float*)d_in[3],  (const float*)d_in[4],  (const float*)d_in[5],
        (const float*)d_in[6],  (const float*)d_in[7],  (const float*)d_in[8],
        (const float*)d_in[9],  (const float*)d_in[10], (const float*)d_in[11],
        (const float*)d_in[12], (const float*)d_in[13], (const float*)d_in[14],
        (const float*)d_in[15], (float*)d_out);
}